// round 1
// baseline (speedup 1.0000x reference)
#include <cuda_runtime.h>
#include <cuda_bf16.h>
#include <math.h>

#define LDIM 4096
#define HDIM 64
#define BDIM 32
#define BH   2048     // BDIM*HDIM
#define NK   128      // 64 real + 64 imag
#define KSPLIT 16
#define KC   256      // LDIM / KSPLIT

// ---------------- device scratch (no allocations allowed) ----------------
__device__ float g_x0[(size_t)BH * LDIM];           // 32 MB
__device__ float g_x1[(size_t)BH * LDIM];           // 32 MB
__device__ float g_cpart[(size_t)KSPLIT * BH * NK]; // 16 MB
__device__ float g_xfT[(size_t)NK * BH];            // 1 MB   [kk][bh]
__device__ float g_g[(size_t)BH * NK];              // 1 MB   [b*64+o][kk]
__device__ float g_trigF[(size_t)LDIM * NK];        // 2 MB   [l][kk]
__device__ float g_trigI[(size_t)NK * LDIM];        // 2 MB   [kk][l]

__device__ __forceinline__ float gelu_tanh(float v) {
    const float c0 = 0.7978845608028654f; // sqrt(2/pi)
    float inner = c0 * (v + 0.044715f * v * v * v);
    return 0.5f * v * (1.0f + tanhf(inner));
}

// ---------------- trig tables ----------------
// trigF[l][kk]: kk<64 -> cos(2*pi*kk*l/L); kk>=64 -> -sin(2*pi*(kk-64)*l/L)
// trigI is the [kk][l] transpose of the same values.
__global__ void trig_kernel() {
    int idx = blockIdx.x * 256 + threadIdx.x;   // < 4096*128
    int l = idx >> 7, kk = idx & 127;
    int k = kk & 63;
    int m = (k * l) & (LDIM - 1);               // angle mod 2*pi, exact
    float sn, cn;
    sincospif((float)m * (1.0f / 2048.0f), &sn, &cn);
    float v = (kk < 64) ? cn : -sn;
    g_trigF[(size_t)l * NK + kk] = v;
    g_trigI[(size_t)kk * LDIM + l] = v;
}

// ---------------- lift: x0[b*64+h][l] = W_lift @ [u;z] + b ----------------
__global__ __launch_bounds__(128) void lift_kernel(
    const float* __restrict__ u, const float* __restrict__ z,
    const float* __restrict__ w_lift, const float* __restrict__ b_lift,
    float* __restrict__ x0)
{
    int b = blockIdx.y;
    int l = blockIdx.x * 128 + threadIdx.x;
    __shared__ float sw[64 * 16];
    __shared__ float sb[64];
    int t = threadIdx.x;
    for (int e = t; e < 1024; e += 128) sw[e] = w_lift[e];
    if (t < 64) sb[t] = b_lift[t];
    __syncthreads();
    float uv[16];
#pragma unroll
    for (int c = 0; c < 8; c++) uv[c] = u[((size_t)b * LDIM + l) * 8 + c];
#pragma unroll
    for (int c = 0; c < 8; c++) uv[8 + c] = z[b * 8 + c];
    for (int h = 0; h < 64; h++) {
        float acc = sb[h];
#pragma unroll
        for (int c = 0; c < 16; c++) acc += sw[h * 16 + c] * uv[c];
        x0[((size_t)(b * 64 + h)) * LDIM + l] = acc;
    }
}

// ---------------- forward DFT (truncated to 64 modes), split-K GEMM ------
// C[bh][kk] = sum_l x[bh][l] * trigF[l][kk];  partial sums per K-split.
__global__ __launch_bounds__(256) void dft_kernel(
    const float* __restrict__ x, float* __restrict__ cpart)
{
    __shared__ float As[16][129];  // [k][bh_local]
    __shared__ float Bs[16][132];  // [k][kk]
    int bh0 = blockIdx.x * 128;
    int l0  = blockIdx.y * KC;
    int t = threadIdx.x;
    int cx = t & 15, ry = t >> 4;  // ry 0..15
    float acc[8][8];
#pragma unroll
    for (int i = 0; i < 8; i++)
#pragma unroll
        for (int j = 0; j < 8; j++) acc[i][j] = 0.f;

    for (int kt = 0; kt < KC; kt += 16) {
#pragma unroll
        for (int e = 0; e < 8; e++) {
            int idx = t + 256 * e;
            int r = idx >> 4, c = idx & 15;
            As[c][r] = x[(size_t)(bh0 + r) * LDIM + l0 + kt + c];
        }
#pragma unroll
        for (int e = 0; e < 8; e++) {
            int idx = t + 256 * e;
            int kk = idx & 127, k = idx >> 7;
            Bs[k][kk] = g_trigF[(size_t)(l0 + kt + k) * NK + kk];
        }
        __syncthreads();
#pragma unroll
        for (int k = 0; k < 16; k++) {
            float a[8], bb[8];
#pragma unroll
            for (int i = 0; i < 8; i++) a[i] = As[k][ry + 16 * i];
#pragma unroll
            for (int j = 0; j < 8; j++) bb[j] = Bs[k][cx + 16 * j];
#pragma unroll
            for (int i = 0; i < 8; i++)
#pragma unroll
                for (int j = 0; j < 8; j++) acc[i][j] += a[i] * bb[j];
        }
        __syncthreads();
    }
    float* cp = cpart + (size_t)blockIdx.y * BH * NK;
#pragma unroll
    for (int i = 0; i < 8; i++) {
        int bh = bh0 + ry + 16 * i;
#pragma unroll
        for (int j = 0; j < 8; j++)
            cp[(size_t)bh * NK + cx + 16 * j] = acc[i][j];
    }
}

// reduce split buffers -> xfT[kk][bh] (deterministic order)
__global__ __launch_bounds__(256) void reduce_kernel(
    const float* __restrict__ cpart, float* __restrict__ xfT)
{
    int idx = blockIdx.x * 256 + threadIdx.x;  // 0..262143
    int bh = idx >> 7, kk = idx & 127;
    float s = 0.f;
#pragma unroll
    for (int p = 0; p < KSPLIT; p++) s += cpart[(size_t)p * BH * NK + idx];
    xfT[(size_t)kk * BH + bh] = s;
}

// ---------------- per-mode complex mix + irfft scaling -------------------
// g[(b*64+o)][k]      = scale_k * Re(sum_i xf[b,i,k]*w[o,i,k])
// g[(b*64+o)][64+k]   = scale_k * Im(...)   (0 for k==0: c2r ignores DC imag)
__global__ __launch_bounds__(256) void mix_kernel(
    const float* __restrict__ xfT, const float* __restrict__ wr,
    const float* __restrict__ wi, float* __restrict__ g, int layer)
{
    int k = blockIdx.x;      // 0..63
    int bg = blockIdx.y;     // 0..1  (16 b each)
    __shared__ float swr[64][65];
    __shared__ float swi[64][65];
    __shared__ float sxr[64][16];
    __shared__ float sxi[64][16];
    int t = threadIdx.x;
    for (int e = t; e < 4096; e += 256) {
        int o = e >> 6, i = e & 63;
        size_t off = ((size_t)(layer * 64 + o) * 64 + i) * 64 + k;
        swr[o][i] = wr[off];
        swi[o][i] = wi[off];
    }
    for (int e = t; e < 1024; e += 256) {
        int b = e >> 6, i = e & 63;
        int bh = (bg * 16 + b) * 64 + i;
        sxr[i][b] = xfT[(size_t)k * BH + bh];
        sxi[i][b] = xfT[(size_t)(64 + k) * BH + bh];
    }
    __syncthreads();
    int o = t >> 2;
    int b0 = (t & 3) * 4;
    float ar[4] = {0, 0, 0, 0}, ai[4] = {0, 0, 0, 0};
    for (int i = 0; i < 64; i++) {
        float wrv = swr[o][i], wiv = swi[o][i];
#pragma unroll
        for (int j = 0; j < 4; j++) {
            float xr = sxr[i][b0 + j], xi = sxi[i][b0 + j];
            ar[j] += xr * wrv - xi * wiv;
            ai[j] += xr * wiv + xi * wrv;
        }
    }
    float scl = (k == 0) ? (1.0f / LDIM) : (2.0f / LDIM);
#pragma unroll
    for (int j = 0; j < 4; j++) {
        int b = bg * 16 + b0 + j;
        g[((size_t)(b * 64 + o)) * NK + k] = ar[j] * scl;
        g[((size_t)(b * 64 + o)) * NK + 64 + k] = (k == 0) ? 0.0f : ai[j] * scl;
    }
}

// ---------------- fused iDFT + skip + bias + gelu ------------------------
// x_new[b,o,l] = gelu( sum_{kk<128} g[b,o,kk]*trigI[kk][l]
//                    + sum_i w_skip[o,i]*x_old[b,i,l] + b_skip[o] )
__global__ __launch_bounds__(256) void idft_kernel(
    const float* __restrict__ g, const float* __restrict__ xold,
    const float* __restrict__ w_skip, const float* __restrict__ b_skip,
    float* __restrict__ xnew, int layer)
{
    int b  = blockIdx.y;
    int l0 = blockIdx.x * 128;
    __shared__ float As[16][65];   // [k][o]
    __shared__ float Bs[16][132];  // [k][l]
    int t = threadIdx.x;
    int lx = t & 31;
    int oy = t >> 5;  // 0..7
    float acc[8][4];
#pragma unroll
    for (int oi = 0; oi < 8; oi++) {
        float bs = b_skip[layer * 64 + oy + 8 * oi];
#pragma unroll
        for (int lj = 0; lj < 4; lj++) acc[oi][lj] = bs;
    }
    for (int kt = 0; kt < 192; kt += 16) {
#pragma unroll
        for (int e = 0; e < 4; e++) {
            int idx = t + 256 * e;    // 0..1023
            int o = idx >> 4, kloc = idx & 15;
            int kk = kt + kloc;
            float v;
            if (kk < 128) v = g[((size_t)(b * 64 + o)) * NK + kk];
            else          v = w_skip[((size_t)layer * 64 + o) * 64 + (kk - 128)];
            As[kloc][o] = v;
        }
#pragma unroll
        for (int e = 0; e < 8; e++) {
            int idx = t + 256 * e;    // 0..2047
            int l = idx & 127, kloc = idx >> 7;
            int kk = kt + kloc;
            const float* src = (kk < 128)
                ? (g_trigI + (size_t)kk * LDIM + l0)
                : (xold + ((size_t)(b * 64 + (kk - 128))) * LDIM + l0);
            Bs[kloc][l] = src[l];
        }
        __syncthreads();
#pragma unroll
        for (int k = 0; k < 16; k++) {
            float av[8], bv[4];
#pragma unroll
            for (int oi = 0; oi < 8; oi++) av[oi] = As[k][oy + 8 * oi];
#pragma unroll
            for (int lj = 0; lj < 4; lj++) bv[lj] = Bs[k][lx + 32 * lj];
#pragma unroll
            for (int oi = 0; oi < 8; oi++)
#pragma unroll
                for (int lj = 0; lj < 4; lj++) acc[oi][lj] += av[oi] * bv[lj];
        }
        __syncthreads();
    }
#pragma unroll
    for (int oi = 0; oi < 8; oi++) {
        int o = oy + 8 * oi;
#pragma unroll
        for (int lj = 0; lj < 4; lj++) {
            float v = gelu_tanh(acc[oi][lj]);
            xnew[((size_t)(b * 64 + o)) * LDIM + l0 + lx + 32 * lj] = v;
        }
    }
}

// ---------------- layer-3 point eval at l=L-1 + projection ---------------
__global__ __launch_bounds__(128) void final_kernel(
    const float* __restrict__ g, const float* __restrict__ x3,
    const float* __restrict__ w_skip, const float* __restrict__ b_skip,
    const float* __restrict__ w_p1, const float* __restrict__ b_p1,
    const float* __restrict__ w_p2, const float* __restrict__ b_p2,
    float* __restrict__ out)
{
    int b = blockIdx.x;
    int t = threadIdx.x;  // 128
    __shared__ float sv[64];
    __shared__ float sh[128];
    __shared__ float sxl[64];
    __shared__ float sc[64], ss[64];
    if (t < 64) {
        sxl[t] = x3[((size_t)(b * 64 + t)) * LDIM + (LDIM - 1)];
        // at l = L-1: cos(2pi k (L-1)/L) = cos(2pi k/L), sin(...) = -sin(2pi k/L)
        float sn, cn;
        sincospif((float)t / 2048.0f, &sn, &cn);
        sc[t] = cn; ss[t] = sn;
    }
    __syncthreads();
    if (t < 64) {
        int o = t;
        float acc = b_skip[3 * 64 + o];
        const float* go = g + ((size_t)(b * 64 + o)) * NK;
        for (int k = 0; k < 64; k++)
            acc += go[k] * sc[k] + go[64 + k] * ss[k];  // gr*cos - gi*(-sin)
        for (int i = 0; i < 64; i++)
            acc += w_skip[(3 * 64 + o) * 64 + i] * sxl[i];
        sv[o] = acc;
    }
    __syncthreads();
    {
        int p = t;
        float acc = b_p1[p];
        for (int o = 0; o < 64; o++) acc += w_p1[p * 64 + o] * sv[o];
        sh[p] = gelu_tanh(acc);
    }
    __syncthreads();
    if (t < 8) {
        float acc = b_p2[t];
        for (int p = 0; p < 128; p++) acc += w_p2[t * 128 + p] * sh[p];
        out[b * 8 + t] = acc;
    }
}

// ---------------- host launcher ------------------------------------------
extern "C" void kernel_launch(void* const* d_in, const int* in_sizes, int n_in,
                              void* d_out, int out_size)
{
    const float* u       = (const float*)d_in[0];
    const float* z       = (const float*)d_in[1];
    // d_in[2] = t  (unused by reference)
    const float* w_lift  = (const float*)d_in[3];
    const float* b_lift  = (const float*)d_in[4];
    const float* spec_wr = (const float*)d_in[5];
    const float* spec_wi = (const float*)d_in[6];
    const float* w_skip  = (const float*)d_in[7];
    const float* b_skip  = (const float*)d_in[8];
    const float* w_p1    = (const float*)d_in[9];
    const float* b_p1    = (const float*)d_in[10];
    const float* w_p2    = (const float*)d_in[11];
    const float* b_p2    = (const float*)d_in[12];
    float* out = (float*)d_out;

    void *px0, *px1, *pcp, *pxf, *pgg;
    cudaGetSymbolAddress(&px0, g_x0);
    cudaGetSymbolAddress(&px1, g_x1);
    cudaGetSymbolAddress(&pcp, g_cpart);
    cudaGetSymbolAddress(&pxf, g_xfT);
    cudaGetSymbolAddress(&pgg, g_g);

    trig_kernel<<<(LDIM * NK) / 256, 256>>>();
    lift_kernel<<<dim3(32, 32), 128>>>(u, z, w_lift, b_lift, (float*)px0);

    float* xcur  = (float*)px0;
    float* xnext = (float*)px1;
    for (int layer = 0; layer < 4; layer++) {
        dft_kernel<<<dim3(16, KSPLIT), 256>>>(xcur, (float*)pcp);
        reduce_kernel<<<(BH * NK) / 256, 256>>>((float*)pcp, (float*)pxf);
        mix_kernel<<<dim3(64, 2), 256>>>((float*)pxf, spec_wr, spec_wi,
                                         (float*)pgg, layer);
        if (layer < 3) {
            idft_kernel<<<dim3(32, 32), 256>>>((float*)pgg, xcur, w_skip,
                                               b_skip, xnext, layer);
            float* tmp = xcur; xcur = xnext; xnext = tmp;
        }
    }
    final_kernel<<<32, 128>>>((float*)pgg, xcur, w_skip, b_skip,
                              w_p1, b_p1, w_p2, b_p2, out);
}

// round 2
// speedup vs baseline: 1.1619x; 1.1619x over previous
#include <cuda_runtime.h>
#include <cuda_bf16.h>
#include <math.h>

#define LDIM 4096
#define HDIM 64
#define BDIM 32
#define BH   2048     // BDIM*HDIM
#define NK   128      // 64 real + 64 imag
#define KSPLIT 16
#define KC   256      // LDIM / KSPLIT

typedef unsigned long long u64;

__device__ __forceinline__ u64 pack2(float lo, float hi) {
    u64 r; asm("mov.b64 %0, {%1,%2};" : "=l"(r) : "f"(lo), "f"(hi)); return r;
}
__device__ __forceinline__ u64 fma2(u64 a, u64 b, u64 c) {
    u64 d; asm("fma.rn.f32x2 %0, %1, %2, %3;" : "=l"(d) : "l"(a), "l"(b), "l"(c));
    return d;
}
__device__ __forceinline__ float2 unpack2(u64 v) {
    float2 f; asm("mov.b64 {%0,%1}, %2;" : "=f"(f.x), "=f"(f.y) : "l"(v)); return f;
}

// ---------------- device scratch (no allocations allowed) ----------------
__device__ float g_x0[(size_t)BH * LDIM];           // 32 MB
__device__ float g_x1[(size_t)BH * LDIM];           // 32 MB
__device__ float g_cpart[(size_t)KSPLIT * BH * NK]; // 16 MB
__device__ float g_xfT[(size_t)NK * BH];            // 1 MB   [kk][bh]
__device__ float g_g[(size_t)BH * NK];              // 1 MB   [b*64+o][kk]
__device__ float g_trigF[(size_t)LDIM * NK];        // 2 MB   [l][kk]
__device__ float g_trigI[(size_t)NK * LDIM];        // 2 MB   [kk][l]

__device__ __forceinline__ float gelu_tanh(float v) {
    const float c0 = 0.7978845608028654f; // sqrt(2/pi)
    float inner = c0 * (v + 0.044715f * v * v * v);
    return 0.5f * v * (1.0f + tanhf(inner));
}

// ---------------- trig tables ----------------
__global__ void trig_kernel() {
    int idx = blockIdx.x * 256 + threadIdx.x;   // < 4096*128
    int l = idx >> 7, kk = idx & 127;
    int k = kk & 63;
    int m = (k * l) & (LDIM - 1);               // angle mod 2*pi, exact
    float sn, cn;
    sincospif((float)m * (1.0f / 2048.0f), &sn, &cn);
    float v = (kk < 64) ? cn : -sn;
    g_trigF[(size_t)l * NK + kk] = v;
    g_trigI[(size_t)kk * LDIM + l] = v;
}

// ---------------- lift ----------------
__global__ __launch_bounds__(128) void lift_kernel(
    const float* __restrict__ u, const float* __restrict__ z,
    const float* __restrict__ w_lift, const float* __restrict__ b_lift,
    float* __restrict__ x0)
{
    int b = blockIdx.y;
    int l = blockIdx.x * 128 + threadIdx.x;
    __shared__ float sw[64 * 16];
    __shared__ float sb[64];
    int t = threadIdx.x;
    for (int e = t; e < 1024; e += 128) sw[e] = w_lift[e];
    if (t < 64) sb[t] = b_lift[t];
    __syncthreads();
    float uv[16];
#pragma unroll
    for (int c = 0; c < 8; c++) uv[c] = u[((size_t)b * LDIM + l) * 8 + c];
#pragma unroll
    for (int c = 0; c < 8; c++) uv[8 + c] = z[b * 8 + c];
    for (int h = 0; h < 64; h++) {
        float acc = sb[h];
#pragma unroll
        for (int c = 0; c < 16; c++) acc += sw[h * 16 + c] * uv[c];
        x0[((size_t)(b * 64 + h)) * LDIM + l] = acc;
    }
}

// ---------------- forward DFT, split-K GEMM, f32x2 packed -----------------
// C[bh][kk] = sum_l x[bh][l] * trigF[l][kk];  kk packed in pairs.
__global__ __launch_bounds__(256) void dft_kernel(
    const float* __restrict__ x, float* __restrict__ cpart)
{
    __shared__ float2 As2[16][129];  // [k][bh_local], value duplicated {v,v}
    __shared__ float  Bs[16][130];   // [k][kk] (row stride even -> 8B aligned)
    int bh0 = blockIdx.x * 128;
    int l0  = blockIdx.y * KC;
    int t = threadIdx.x;
    int cx = t & 15, ry = t >> 4;    // cx: kk-pair group, ry: bh group
    u64 acc[8][4];
#pragma unroll
    for (int i = 0; i < 8; i++)
#pragma unroll
        for (int j = 0; j < 4; j++) acc[i][j] = 0ull;

    for (int kt = 0; kt < KC; kt += 16) {
#pragma unroll
        for (int e = 0; e < 8; e++) {
            int idx = t + 256 * e;
            int r = idx >> 4, c = idx & 15;
            float v = x[(size_t)(bh0 + r) * LDIM + l0 + kt + c];
            As2[c][r] = make_float2(v, v);
        }
#pragma unroll
        for (int e = 0; e < 8; e++) {
            int idx = t + 256 * e;
            int kk = idx & 127, k = idx >> 7;
            Bs[k][kk] = g_trigF[(size_t)(l0 + kt + k) * NK + kk];
        }
        __syncthreads();
#pragma unroll
        for (int k = 0; k < 16; k++) {
            u64 a2[8], b2[4];
#pragma unroll
            for (int i = 0; i < 8; i++)
                a2[i] = *reinterpret_cast<const u64*>(&As2[k][ry + 16 * i]);
#pragma unroll
            for (int j = 0; j < 4; j++)
                b2[j] = *reinterpret_cast<const u64*>(&Bs[k][2 * (cx + 16 * j)]);
#pragma unroll
            for (int i = 0; i < 8; i++)
#pragma unroll
                for (int j = 0; j < 4; j++)
                    acc[i][j] = fma2(a2[i], b2[j], acc[i][j]);
        }
        __syncthreads();
    }
    float* cp = cpart + (size_t)blockIdx.y * BH * NK;
#pragma unroll
    for (int i = 0; i < 8; i++) {
        int bh = bh0 + ry + 16 * i;
#pragma unroll
        for (int j = 0; j < 4; j++) {
            float2 v = unpack2(acc[i][j]);
            *reinterpret_cast<float2*>(&cp[(size_t)bh * NK + 2 * (cx + 16 * j)]) = v;
        }
    }
}

// reduce split buffers -> xfT[kk][bh], float4 vectorized
__global__ __launch_bounds__(256) void reduce_kernel(
    const float* __restrict__ cpart, float* __restrict__ xfT)
{
    int q = blockIdx.x * 256 + threadIdx.x;     // float4 index, < BH*NK/4
    int idx = q * 4;
    int bh = idx >> 7, kk = idx & 127;
    float4 s = make_float4(0.f, 0.f, 0.f, 0.f);
#pragma unroll
    for (int p = 0; p < KSPLIT; p++) {
        float4 v = *reinterpret_cast<const float4*>(&cpart[(size_t)p * BH * NK + idx]);
        s.x += v.x; s.y += v.y; s.z += v.z; s.w += v.w;
    }
    // scatter to transposed layout [kk][bh]
    xfT[(size_t)(kk + 0) * BH + bh] = s.x;
    xfT[(size_t)(kk + 1) * BH + bh] = s.y;
    xfT[(size_t)(kk + 2) * BH + bh] = s.z;
    xfT[(size_t)(kk + 3) * BH + bh] = s.w;
}

// ---------------- per-mode complex mix + irfft scaling -------------------
__global__ __launch_bounds__(256) void mix_kernel(
    const float* __restrict__ xfT, const float* __restrict__ wr,
    const float* __restrict__ wi, float* __restrict__ g, int layer)
{
    int k = blockIdx.x;      // 0..63
    int bg = blockIdx.y;     // 0..1  (16 b each)
    __shared__ float swr[64][65];
    __shared__ float swi[64][65];
    __shared__ float sxr[64][16];
    __shared__ float sxi[64][16];
    int t = threadIdx.x;
    for (int e = t; e < 4096; e += 256) {
        int o = e >> 6, i = e & 63;
        size_t off = ((size_t)(layer * 64 + o) * 64 + i) * 64 + k;
        swr[o][i] = wr[off];
        swi[o][i] = wi[off];
    }
    for (int e = t; e < 1024; e += 256) {
        int b = e >> 6, i = e & 63;
        int bh = (bg * 16 + b) * 64 + i;
        sxr[i][b] = xfT[(size_t)k * BH + bh];
        sxi[i][b] = xfT[(size_t)(64 + k) * BH + bh];
    }
    __syncthreads();
    int o = t >> 2;
    int b0 = (t & 3) * 4;
    float ar[4] = {0, 0, 0, 0}, ai[4] = {0, 0, 0, 0};
    for (int i = 0; i < 64; i++) {
        float wrv = swr[o][i], wiv = swi[o][i];
#pragma unroll
        for (int j = 0; j < 4; j++) {
            float xr = sxr[i][b0 + j], xi = sxi[i][b0 + j];
            ar[j] += xr * wrv - xi * wiv;
            ai[j] += xr * wiv + xi * wrv;
        }
    }
    float scl = (k == 0) ? (1.0f / LDIM) : (2.0f / LDIM);
#pragma unroll
    for (int j = 0; j < 4; j++) {
        int b = bg * 16 + b0 + j;
        g[((size_t)(b * 64 + o)) * NK + k] = ar[j] * scl;
        g[((size_t)(b * 64 + o)) * NK + 64 + k] = (k == 0) ? 0.0f : ai[j] * scl;
    }
}

// ---------------- fused iDFT + skip + bias + gelu, f32x2 packed ----------
// l tile = 256 (128 pairs), o tile = 64, K = 192.
__global__ __launch_bounds__(256) void idft_kernel(
    const float* __restrict__ g, const float* __restrict__ xold,
    const float* __restrict__ w_skip, const float* __restrict__ b_skip,
    float* __restrict__ xnew, int layer)
{
    __shared__ float2 As2[16][65];   // [k][o], duplicated {v,v}
    __shared__ float2 Bs2[16][129];  // [k][l-pair]
    int b  = blockIdx.y;
    int l0 = blockIdx.x * 256;
    int t = threadIdx.x;
    int lx = t & 31;                 // l-pair group
    int oy = t >> 5;                 // 0..7 (o group)
    u64 acc[8][4];
#pragma unroll
    for (int oi = 0; oi < 8; oi++) {
        float bs = b_skip[layer * 64 + oy + 8 * oi];
        u64 p = pack2(bs, bs);
#pragma unroll
        for (int lj = 0; lj < 4; lj++) acc[oi][lj] = p;
    }
    for (int kt = 0; kt < 192; kt += 16) {
#pragma unroll
        for (int e = 0; e < 4; e++) {
            int idx = t + 256 * e;    // 0..1023
            int o = idx >> 4, kloc = idx & 15;
            int kk = kt + kloc;
            float v;
            if (kk < 128) v = g[((size_t)(b * 64 + o)) * NK + kk];
            else          v = w_skip[((size_t)layer * 64 + o) * 64 + (kk - 128)];
            As2[kloc][o] = make_float2(v, v);
        }
#pragma unroll
        for (int e = 0; e < 8; e++) {
            int idx = t + 256 * e;    // 0..2047
            int lp = idx & 127, kloc = idx >> 7;
            int kk = kt + kloc;
            const float* srow = (kk < 128)
                ? (g_trigI + (size_t)kk * LDIM + l0)
                : (xold + ((size_t)(b * 64 + (kk - 128))) * LDIM + l0);
            Bs2[kloc][lp] = *reinterpret_cast<const float2*>(&srow[2 * lp]);
        }
        __syncthreads();
#pragma unroll
        for (int k = 0; k < 16; k++) {
            u64 a2[8], b2[4];
#pragma unroll
            for (int oi = 0; oi < 8; oi++)
                a2[oi] = *reinterpret_cast<const u64*>(&As2[k][oy + 8 * oi]);
#pragma unroll
            for (int lj = 0; lj < 4; lj++)
                b2[lj] = *reinterpret_cast<const u64*>(&Bs2[k][lx + 32 * lj]);
#pragma unroll
            for (int oi = 0; oi < 8; oi++)
#pragma unroll
                for (int lj = 0; lj < 4; lj++)
                    acc[oi][lj] = fma2(a2[oi], b2[lj], acc[oi][lj]);
        }
        __syncthreads();
    }
#pragma unroll
    for (int oi = 0; oi < 8; oi++) {
        int o = oy + 8 * oi;
#pragma unroll
        for (int lj = 0; lj < 4; lj++) {
            float2 v = unpack2(acc[oi][lj]);
            v.x = gelu_tanh(v.x);
            v.y = gelu_tanh(v.y);
            *reinterpret_cast<float2*>(
                &xnew[((size_t)(b * 64 + o)) * LDIM + l0 + 2 * (lx + 32 * lj)]) = v;
        }
    }
}

// ---------------- layer-3 point eval at l=L-1 + projection ---------------
__global__ __launch_bounds__(128) void final_kernel(
    const float* __restrict__ g, const float* __restrict__ x3,
    const float* __restrict__ w_skip, const float* __restrict__ b_skip,
    const float* __restrict__ w_p1, const float* __restrict__ b_p1,
    const float* __restrict__ w_p2, const float* __restrict__ b_p2,
    float* __restrict__ out)
{
    int b = blockIdx.x;
    int t = threadIdx.x;  // 128
    __shared__ float sv[64];
    __shared__ float sh[128];
    __shared__ float sxl[64];
    __shared__ float sc[64], ss[64];
    if (t < 64) {
        sxl[t] = x3[((size_t)(b * 64 + t)) * LDIM + (LDIM - 1)];
        float sn, cn;
        sincospif((float)t / 2048.0f, &sn, &cn);
        sc[t] = cn; ss[t] = sn;
    }
    __syncthreads();
    if (t < 64) {
        int o = t;
        float acc = b_skip[3 * 64 + o];
        const float* go = g + ((size_t)(b * 64 + o)) * NK;
        for (int k = 0; k < 64; k++)
            acc += go[k] * sc[k] + go[64 + k] * ss[k];
        for (int i = 0; i < 64; i++)
            acc += w_skip[(3 * 64 + o) * 64 + i] * sxl[i];
        sv[o] = acc;
    }
    __syncthreads();
    {
        int p = t;
        float acc = b_p1[p];
        for (int o = 0; o < 64; o++) acc += w_p1[p * 64 + o] * sv[o];
        sh[p] = gelu_tanh(acc);
    }
    __syncthreads();
    if (t < 8) {
        float acc = b_p2[t];
        for (int p = 0; p < 128; p++) acc += w_p2[t * 128 + p] * sh[p];
        out[b * 8 + t] = acc;
    }
}

// ---------------- host launcher ------------------------------------------
extern "C" void kernel_launch(void* const* d_in, const int* in_sizes, int n_in,
                              void* d_out, int out_size)
{
    const float* u       = (const float*)d_in[0];
    const float* z       = (const float*)d_in[1];
    const float* w_lift  = (const float*)d_in[3];
    const float* b_lift  = (const float*)d_in[4];
    const float* spec_wr = (const float*)d_in[5];
    const float* spec_wi = (const float*)d_in[6];
    const float* w_skip  = (const float*)d_in[7];
    const float* b_skip  = (const float*)d_in[8];
    const float* w_p1    = (const float*)d_in[9];
    const float* b_p1    = (const float*)d_in[10];
    const float* w_p2    = (const float*)d_in[11];
    const float* b_p2    = (const float*)d_in[12];
    float* out = (float*)d_out;

    void *px0, *px1, *pcp, *pxf, *pgg;
    cudaGetSymbolAddress(&px0, g_x0);
    cudaGetSymbolAddress(&px1, g_x1);
    cudaGetSymbolAddress(&pcp, g_cpart);
    cudaGetSymbolAddress(&pxf, g_xfT);
    cudaGetSymbolAddress(&pgg, g_g);

    trig_kernel<<<(LDIM * NK) / 256, 256>>>();
    lift_kernel<<<dim3(32, 32), 128>>>(u, z, w_lift, b_lift, (float*)px0);

    float* xcur  = (float*)px0;
    float* xnext = (float*)px1;
    for (int layer = 0; layer < 4; layer++) {
        dft_kernel<<<dim3(16, KSPLIT), 256>>>(xcur, (float*)pcp);
        reduce_kernel<<<(BH * NK / 4) / 256, 256>>>((float*)pcp, (float*)pxf);
        mix_kernel<<<dim3(64, 2), 256>>>((float*)pxf, spec_wr, spec_wi,
                                         (float*)pgg, layer);
        if (layer < 3) {
            idft_kernel<<<dim3(16, 32), 256>>>((float*)pgg, xcur, w_skip,
                                               b_skip, xnext, layer);
            float* tmp = xcur; xcur = xnext; xnext = tmp;
        }
    }
    final_kernel<<<32, 128>>>((float*)pgg, xcur, w_skip, b_skip,
                              w_p1, b_p1, w_p2, b_p2, out);
}

// round 3
// speedup vs baseline: 1.2824x; 1.1037x over previous
#include <cuda_runtime.h>
#include <cuda_bf16.h>
#include <math.h>

#define LDIM 4096
#define HDIM 64
#define BDIM 32
#define BH   2048     // BDIM*HDIM
#define NK   128      // 64 real + 64 imag
#define KSPLIT 16
#define KC   256      // LDIM / KSPLIT

typedef unsigned long long u64;

__device__ __forceinline__ u64 pack2(float lo, float hi) {
    u64 r; asm("mov.b64 %0, {%1,%2};" : "=l"(r) : "f"(lo), "f"(hi)); return r;
}
__device__ __forceinline__ u64 fma2(u64 a, u64 b, u64 c) {
    u64 d; asm("fma.rn.f32x2 %0, %1, %2, %3;" : "=l"(d) : "l"(a), "l"(b), "l"(c));
    return d;
}
__device__ __forceinline__ float2 unpack2(u64 v) {
    float2 f; asm("mov.b64 {%0,%1}, %2;" : "=f"(f.x), "=f"(f.y) : "l"(v)); return f;
}

// ---------------- device scratch ----------------
__device__ float g_x0[(size_t)BH * LDIM];           // 32 MB
__device__ float g_x1[(size_t)BH * LDIM];           // 32 MB
__device__ float g_cpart[(size_t)KSPLIT * BH * NK]; // 16 MB
__device__ float g_xfT[(size_t)NK * BH];            // 1 MB   [kk][bh]
__device__ float g_g[(size_t)BH * NK];              // 1 MB   [b*64+o][kk]
__device__ float g_trigF[(size_t)LDIM * NK];        // 2 MB   [l][kk]
__device__ float g_trigI[(size_t)NK * LDIM];        // 2 MB   [kk][l]
__device__ float g_wT[(size_t)4 * 64 * 2 * 4096];   // 8 MB   [layer][k][ri][o*64+i]

__device__ __forceinline__ float gelu_tanh(float v) {
    const float c0 = 0.7978845608028654f;
    float inner = c0 * (v + 0.044715f * v * v * v);
    return 0.5f * v * (1.0f + tanhf(inner));
}
__device__ __forceinline__ float gelu_fast(float v) {
    const float c0 = 0.7978845608028654f;
    float inner = c0 * (v + 0.044715f * v * v * v);
    float th;
    asm("tanh.approx.f32 %0, %1;" : "=f"(th) : "f"(inner));
    return 0.5f * v * (1.0f + th);
}

// ---------------- trig tables ----------------
__global__ void trig_kernel() {
    int idx = blockIdx.x * 256 + threadIdx.x;   // < 4096*128
    int l = idx >> 7, kk = idx & 127;
    int k = kk & 63;
    int m = (k * l) & (LDIM - 1);
    float sn, cn;
    sincospif((float)m * (1.0f / 2048.0f), &sn, &cn);
    float v = (kk < 64) ? cn : -sn;
    g_trigF[(size_t)l * NK + kk] = v;
    g_trigI[(size_t)kk * LDIM + l] = v;
}

// ---------------- spec weight transpose: [l][o][i][k] -> [l][k][ri][o*64+i]
__global__ __launch_bounds__(1024) void wtrans_kernel(
    const float* __restrict__ wr, const float* __restrict__ wi)
{
    __shared__ float tr[32][33];
    __shared__ float ti[32][33];
    int oi0 = blockIdx.x * 32;
    int k0  = blockIdx.y * 32;
    int layer = blockIdx.z;
    int tx = threadIdx.x & 31, ty = threadIdx.x >> 5;
    size_t rbase = ((size_t)layer * 4096 + oi0 + ty) * 64 + k0 + tx;
    tr[ty][tx] = wr[rbase];
    ti[ty][tx] = wi[rbase];
    __syncthreads();
    int k = k0 + ty;
    size_t wbase = ((size_t)(layer * 64 + k) * 2) * 4096 + oi0 + tx;
    g_wT[wbase]        = tr[tx][ty];
    g_wT[wbase + 4096] = ti[tx][ty];
}

// ---------------- lift ----------------
__global__ __launch_bounds__(128) void lift_kernel(
    const float* __restrict__ u, const float* __restrict__ z,
    const float* __restrict__ w_lift, const float* __restrict__ b_lift,
    float* __restrict__ x0)
{
    int b = blockIdx.y;
    int l = blockIdx.x * 128 + threadIdx.x;
    __shared__ float sw[64 * 16];
    __shared__ float sb[64];
    int t = threadIdx.x;
    for (int e = t; e < 1024; e += 128) sw[e] = w_lift[e];
    if (t < 64) sb[t] = b_lift[t];
    __syncthreads();
    float uv[16];
#pragma unroll
    for (int c = 0; c < 8; c++) uv[c] = u[((size_t)b * LDIM + l) * 8 + c];
#pragma unroll
    for (int c = 0; c < 8; c++) uv[8 + c] = z[b * 8 + c];
    for (int h = 0; h < 64; h++) {
        float acc = sb[h];
#pragma unroll
        for (int c = 0; c < 16; c++) acc += sw[h * 16 + c] * uv[c];
        x0[((size_t)(b * 64 + h)) * LDIM + l] = acc;
    }
}

// ---------------- forward DFT, split-K GEMM, f32x2, 8x8 tiles ------------
// CTA: 256 bh x 128 kk, K-chunk = KC. cx = kk-pair group (8), ry = bh (32).
__global__ __launch_bounds__(256) void dft_kernel(
    const float* __restrict__ x, float* __restrict__ cpart)
{
    __shared__ float2 As2[16][257];  // [k][bh_local] duplicated {v,v}
    __shared__ float  Bs[16][130];   // [k][kk]
    int bh0 = blockIdx.x * 256;
    int l0  = blockIdx.y * KC;
    int t = threadIdx.x;
    int cx = t & 7, ry = t >> 3;
    u64 acc[8][8];
#pragma unroll
    for (int i = 0; i < 8; i++)
#pragma unroll
        for (int j = 0; j < 8; j++) acc[i][j] = 0ull;

    float xa[16], tb[8];
    // prologue: load k-tile 0 into registers
#pragma unroll
    for (int e = 0; e < 16; e++) {
        int idx = t + 256 * e;
        int r = idx >> 4, c = idx & 15;
        xa[e] = x[(size_t)(bh0 + r) * LDIM + l0 + c];
    }
#pragma unroll
    for (int e = 0; e < 8; e++) {
        int idx = t + 256 * e;
        int kk = idx & 127, k = idx >> 7;
        tb[e] = g_trigF[(size_t)(l0 + k) * NK + kk];
    }

    for (int kt = 0; kt < KC; kt += 16) {
#pragma unroll
        for (int e = 0; e < 16; e++) {
            int idx = t + 256 * e;
            int r = idx >> 4, c = idx & 15;
            As2[c][r] = make_float2(xa[e], xa[e]);
        }
#pragma unroll
        for (int e = 0; e < 8; e++) {
            int idx = t + 256 * e;
            int kk = idx & 127, k = idx >> 7;
            Bs[k][kk] = tb[e];
        }
        __syncthreads();
        if (kt + 16 < KC) {
#pragma unroll
            for (int e = 0; e < 16; e++) {
                int idx = t + 256 * e;
                int r = idx >> 4, c = idx & 15;
                xa[e] = x[(size_t)(bh0 + r) * LDIM + l0 + kt + 16 + c];
            }
#pragma unroll
            for (int e = 0; e < 8; e++) {
                int idx = t + 256 * e;
                int kk = idx & 127, k = idx >> 7;
                tb[e] = g_trigF[(size_t)(l0 + kt + 16 + k) * NK + kk];
            }
        }
#pragma unroll
        for (int k = 0; k < 16; k++) {
            u64 a2[8], b2[8];
#pragma unroll
            for (int i = 0; i < 8; i++)
                a2[i] = *reinterpret_cast<const u64*>(&As2[k][ry + 32 * i]);
#pragma unroll
            for (int j = 0; j < 8; j++)
                b2[j] = *reinterpret_cast<const u64*>(&Bs[k][2 * (cx + 8 * j)]);
#pragma unroll
            for (int i = 0; i < 8; i++)
#pragma unroll
                for (int j = 0; j < 8; j++)
                    acc[i][j] = fma2(a2[i], b2[j], acc[i][j]);
        }
        __syncthreads();
    }
    float* cp = cpart + (size_t)blockIdx.y * BH * NK;
#pragma unroll
    for (int i = 0; i < 8; i++) {
        int bh = bh0 + ry + 32 * i;
#pragma unroll
        for (int j = 0; j < 8; j++) {
            float2 v = unpack2(acc[i][j]);
            *reinterpret_cast<float2*>(&cp[(size_t)bh * NK + 2 * (cx + 8 * j)]) = v;
        }
    }
}

// reduce split buffers -> xfT[kk][bh]
__global__ __launch_bounds__(256) void reduce_kernel(
    const float* __restrict__ cpart, float* __restrict__ xfT)
{
    int q = blockIdx.x * 256 + threadIdx.x;
    int idx = q * 4;
    int bh = idx >> 7, kk = idx & 127;
    float4 s = make_float4(0.f, 0.f, 0.f, 0.f);
#pragma unroll
    for (int p = 0; p < KSPLIT; p++) {
        float4 v = *reinterpret_cast<const float4*>(&cpart[(size_t)p * BH * NK + idx]);
        s.x += v.x; s.y += v.y; s.z += v.z; s.w += v.w;
    }
    xfT[(size_t)(kk + 0) * BH + bh] = s.x;
    xfT[(size_t)(kk + 1) * BH + bh] = s.y;
    xfT[(size_t)(kk + 2) * BH + bh] = s.z;
    xfT[(size_t)(kk + 3) * BH + bh] = s.w;
}

// ---------------- per-mode complex mix (coalesced weights) ---------------
__global__ __launch_bounds__(256) void mix_kernel(
    const float* __restrict__ xfT, float* __restrict__ g, int layer)
{
    int k = blockIdx.x;      // 0..63
    int bg = blockIdx.y;     // 0..1
    __shared__ float swr[64][65];
    __shared__ float swi[64][65];
    __shared__ float sxr[64][16];
    __shared__ float sxi[64][16];
    int t = threadIdx.x;
    const float* wTr = g_wT + ((size_t)(layer * 64 + k) * 2) * 4096;
    for (int e = t; e < 4096; e += 256) {
        int o = e >> 6, i = e & 63;
        swr[o][i] = wTr[e];
        swi[o][i] = wTr[4096 + e];
    }
    for (int e = t; e < 1024; e += 256) {
        int b = e >> 6, i = e & 63;
        int bh = (bg * 16 + b) * 64 + i;
        sxr[i][b] = xfT[(size_t)k * BH + bh];
        sxi[i][b] = xfT[(size_t)(64 + k) * BH + bh];
    }
    __syncthreads();
    int o = t >> 2;
    int b0 = (t & 3) * 4;
    float ar[4] = {0, 0, 0, 0}, ai[4] = {0, 0, 0, 0};
    for (int i = 0; i < 64; i++) {
        float wrv = swr[o][i], wiv = swi[o][i];
#pragma unroll
        for (int j = 0; j < 4; j++) {
            float xr = sxr[i][b0 + j], xi = sxi[i][b0 + j];
            ar[j] += xr * wrv - xi * wiv;
            ai[j] += xr * wiv + xi * wrv;
        }
    }
    float scl = (k == 0) ? (1.0f / LDIM) : (2.0f / LDIM);
#pragma unroll
    for (int j = 0; j < 4; j++) {
        int b = bg * 16 + b0 + j;
        g[((size_t)(b * 64 + o)) * NK + k] = ar[j] * scl;
        g[((size_t)(b * 64 + o)) * NK + 64 + k] = (k == 0) ? 0.0f : ai[j] * scl;
    }
}

// ---------------- fused iDFT + skip + bias + gelu, f32x2, 8x8 tiles ------
// CTA: 64 o x 512 l, K = 192. lx = l-pair group (32), oy = o group (8).
__global__ __launch_bounds__(256) void idft_kernel(
    const float* __restrict__ g, const float* __restrict__ xold,
    const float* __restrict__ w_skip, const float* __restrict__ b_skip,
    float* __restrict__ xnew, int layer)
{
    __shared__ float2 As2[16][65];   // [k][o] duplicated {v,v}
    __shared__ float2 Bs2[16][257];  // [k][l-pair]
    int b  = blockIdx.y;
    int l0 = blockIdx.x * 512;
    int t = threadIdx.x;
    int lx = t & 31;
    int oy = t >> 5;
    u64 acc[8][8];
#pragma unroll
    for (int oi = 0; oi < 8; oi++) {
        float bs = b_skip[layer * 64 + oy + 8 * oi];
        u64 p = pack2(bs, bs);
#pragma unroll
        for (int lj = 0; lj < 8; lj++) acc[oi][lj] = p;
    }
    float av[4];
    float2 bv[16];
    // prologue loads (kt = 0)
#pragma unroll
    for (int e = 0; e < 4; e++) {
        int idx = t + 256 * e;
        int o = idx >> 4, kloc = idx & 15;
        av[e] = g[((size_t)(b * 64 + o)) * NK + kloc];  // kt=0 < 128 always
    }
#pragma unroll
    for (int e = 0; e < 16; e++) {
        bv[e] = *reinterpret_cast<const float2*>(
            &g_trigI[(size_t)e * LDIM + l0 + 2 * t]);
    }

    for (int kt = 0; kt < 192; kt += 16) {
#pragma unroll
        for (int e = 0; e < 4; e++) {
            int idx = t + 256 * e;
            int o = idx >> 4, kloc = idx & 15;
            As2[kloc][o] = make_float2(av[e], av[e]);
        }
#pragma unroll
        for (int e = 0; e < 16; e++) Bs2[e][t] = bv[e];
        __syncthreads();
        if (kt + 16 < 192) {
            int kn = kt + 16;
#pragma unroll
            for (int e = 0; e < 4; e++) {
                int idx = t + 256 * e;
                int o = idx >> 4, kloc = idx & 15;
                int kk = kn + kloc;
                av[e] = (kk < 128)
                    ? g[((size_t)(b * 64 + o)) * NK + kk]
                    : w_skip[((size_t)layer * 64 + o) * 64 + (kk - 128)];
            }
#pragma unroll
            for (int e = 0; e < 16; e++) {
                int kk = kn + e;
                const float* srow = (kk < 128)
                    ? (g_trigI + (size_t)kk * LDIM + l0)
                    : (xold + ((size_t)(b * 64 + (kk - 128))) * LDIM + l0);
                bv[e] = *reinterpret_cast<const float2*>(&srow[2 * t]);
            }
        }
#pragma unroll
        for (int k = 0; k < 16; k++) {
            u64 a2[8], b2[8];
#pragma unroll
            for (int oi = 0; oi < 8; oi++)
                a2[oi] = *reinterpret_cast<const u64*>(&As2[k][oy + 8 * oi]);
#pragma unroll
            for (int lj = 0; lj < 8; lj++)
                b2[lj] = *reinterpret_cast<const u64*>(&Bs2[k][lx + 32 * lj]);
#pragma unroll
            for (int oi = 0; oi < 8; oi++)
#pragma unroll
                for (int lj = 0; lj < 8; lj++)
                    acc[oi][lj] = fma2(a2[oi], b2[lj], acc[oi][lj]);
        }
        __syncthreads();
    }
#pragma unroll
    for (int oi = 0; oi < 8; oi++) {
        int o = oy + 8 * oi;
#pragma unroll
        for (int lj = 0; lj < 8; lj++) {
            float2 v = unpack2(acc[oi][lj]);
            v.x = gelu_fast(v.x);
            v.y = gelu_fast(v.y);
            *reinterpret_cast<float2*>(
                &xnew[((size_t)(b * 64 + o)) * LDIM + l0 + 2 * (lx + 32 * lj)]) = v;
        }
    }
}

// ---------------- layer-3 point eval at l=L-1 + projection ---------------
__global__ __launch_bounds__(128) void final_kernel(
    const float* __restrict__ g, const float* __restrict__ x3,
    const float* __restrict__ w_skip, const float* __restrict__ b_skip,
    const float* __restrict__ w_p1, const float* __restrict__ b_p1,
    const float* __restrict__ w_p2, const float* __restrict__ b_p2,
    float* __restrict__ out)
{
    int b = blockIdx.x;
    int t = threadIdx.x;  // 128
    __shared__ float sv[64];
    __shared__ float sh[128];
    __shared__ float sxl[64];
    __shared__ float sc[64], ss[64];
    if (t < 64) {
        sxl[t] = x3[((size_t)(b * 64 + t)) * LDIM + (LDIM - 1)];
        float sn, cn;
        sincospif((float)t / 2048.0f, &sn, &cn);
        sc[t] = cn; ss[t] = sn;
    }
    __syncthreads();
    if (t < 64) {
        int o = t;
        float acc = b_skip[3 * 64 + o];
        const float* go = g + ((size_t)(b * 64 + o)) * NK;
        for (int k = 0; k < 64; k++)
            acc += go[k] * sc[k] + go[64 + k] * ss[k];
        for (int i = 0; i < 64; i++)
            acc += w_skip[(3 * 64 + o) * 64 + i] * sxl[i];
        sv[o] = acc;
    }
    __syncthreads();
    {
        int p = t;
        float acc = b_p1[p];
        for (int o = 0; o < 64; o++) acc += w_p1[p * 64 + o] * sv[o];
        sh[p] = gelu_tanh(acc);
    }
    __syncthreads();
    if (t < 8) {
        float acc = b_p2[t];
        for (int p = 0; p < 128; p++) acc += w_p2[t * 128 + p] * sh[p];
        out[b * 8 + t] = acc;
    }
}

// ---------------- host launcher ------------------------------------------
extern "C" void kernel_launch(void* const* d_in, const int* in_sizes, int n_in,
                              void* d_out, int out_size)
{
    const float* u       = (const float*)d_in[0];
    const float* z       = (const float*)d_in[1];
    const float* w_lift  = (const float*)d_in[3];
    const float* b_lift  = (const float*)d_in[4];
    const float* spec_wr = (const float*)d_in[5];
    const float* spec_wi = (const float*)d_in[6];
    const float* w_skip  = (const float*)d_in[7];
    const float* b_skip  = (const float*)d_in[8];
    const float* w_p1    = (const float*)d_in[9];
    const float* b_p1    = (const float*)d_in[10];
    const float* w_p2    = (const float*)d_in[11];
    const float* b_p2    = (const float*)d_in[12];
    float* out = (float*)d_out;

    void *px0, *px1, *pcp, *pxf, *pgg;
    cudaGetSymbolAddress(&px0, g_x0);
    cudaGetSymbolAddress(&px1, g_x1);
    cudaGetSymbolAddress(&pcp, g_cpart);
    cudaGetSymbolAddress(&pxf, g_xfT);
    cudaGetSymbolAddress(&pgg, g_g);

    trig_kernel<<<(LDIM * NK) / 256, 256>>>();
    wtrans_kernel<<<dim3(128, 2, 4), 1024>>>(spec_wr, spec_wi);
    lift_kernel<<<dim3(32, 32), 128>>>(u, z, w_lift, b_lift, (float*)px0);

    float* xcur  = (float*)px0;
    float* xnext = (float*)px1;
    for (int layer = 0; layer < 4; layer++) {
        dft_kernel<<<dim3(8, KSPLIT), 256>>>(xcur, (float*)pcp);
        reduce_kernel<<<(BH * NK / 4) / 256, 256>>>((float*)pcp, (float*)pxf);
        mix_kernel<<<dim3(64, 2), 256>>>((float*)pxf, (float*)pgg, layer);
        if (layer < 3) {
            idft_kernel<<<dim3(8, 32), 256>>>((float*)pgg, xcur, w_skip,
                                              b_skip, xnext, layer);
            float* tmp = xcur; xcur = xnext; xnext = tmp;
        }
    }
    final_kernel<<<32, 128>>>((float*)pgg, xcur, w_skip, b_skip,
                              w_p1, b_p1, w_p2, b_p2, out);
}